// round 16
// baseline (speedup 1.0000x reference)
#include <cuda_runtime.h>
#include <cuda_fp16.h>
#include <cstdint>

#define NPTS 8192
#define DIMX 256
#define DIMZ 64
#define KNN  5
#define EPSF 1e-7f

#define NTILE 128                          // 8192 / 64 row-tiles
#define NPAIRS (NTILE * (NTILE + 1) / 2)   // 8256
#define PTOP 4
#define GTOP 8
#define U32MAX 0xFFFFFFFFu
#define IDXMASK 0x1FFFu                    // 13 bits: idx < 8192

// ---- scratch ----
__device__ float g_sq[NPTS];
__device__ __half g_xh[NPTS * DIMX];          // fp16 copy of X (4 MB)
__device__ uint4 g_p[(size_t)NPTS * NTILE];   // 16.8 MB: 4 packed u32 keys per (row,tile)
__device__ float g_bsum[1024];

__device__ __forceinline__ uint32_t smem_u32(const void* p) {
    uint32_t a;
    asm("{ .reg .u64 t; cvta.to.shared.u64 t, %1; cvt.u32.u64 %0, t; }" : "=r"(a) : "l"(p));
    return a;
}

#define LDSM_X4(r0, r1, r2, r3, addr) \
    asm volatile("ldmatrix.sync.aligned.m8n8.x4.shared.b16 {%0,%1,%2,%3}, [%4];" \
                 : "=r"(r0), "=r"(r1), "=r"(r2), "=r"(r3) : "r"(addr))

// f16 inputs, f16 accumulators (2 .f16x2 D regs)
#define MMA16816H(d, a0, a1, a2, a3, b0, b1) \
    asm volatile("mma.sync.aligned.m16n8k16.row.col.f16.f16.f16.f16 " \
                 "{%0,%1}, {%2,%3,%4,%5}, {%6,%7}, {%0,%1};" \
                 : "+r"((d)[0]), "+r"((d)[1]) \
                 : "r"(a0), "r"(a1), "r"(a2), "r"(a3), "r"(b0), "r"(b1))

// monotone float->u32, top 19 bits kept; low 13 bits = idx.
// u32 '<' == (quantized value, idx) lexicographic.
__device__ __forceinline__ uint32_t packkey32(float v, int idx) {
    uint32_t u = __float_as_uint(v);
    u = (u >> 31) ? ~u : (u | 0x80000000u);
    return (u & ~IDXMASK) | (uint32_t)idx;
}
template<int NL>
__device__ __forceinline__ void insertK(uint32_t l[NL], uint32_t v) {
    if (v < l[NL - 1]) {
        l[NL - 1] = v;
#pragma unroll
        for (int s = NL - 1; s > 0; --s)
            if (l[s] < l[s - 1]) { uint32_t t = l[s]; l[s] = l[s - 1]; l[s - 1] = t; }
    }
}
__device__ __forceinline__ bool lessp(float v, int i, float v2, int i2) {
    return (v < v2) || (v == v2 && i < i2);
}
__device__ __forceinline__ void insert5(float lv[KNN], int li[KNN], float v, int idx) {
    if (lessp(v, idx, lv[KNN - 1], li[KNN - 1])) {
        lv[KNN - 1] = v; li[KNN - 1] = idx;
#pragma unroll
        for (int s = KNN - 1; s > 0; --s) {
            if (lessp(lv[s], li[s], lv[s - 1], li[s - 1])) {
                float tv = lv[s]; lv[s] = lv[s - 1]; lv[s - 1] = tv;
                int   ti = li[s]; li[s] = li[s - 1]; li[s - 1] = ti;
            }
        }
    }
}

// ================= fused fp32->fp16 + squared row norms =================
__global__ void cvtsq_kernel(const float* __restrict__ X) {
    int warp = (blockIdx.x * blockDim.x + threadIdx.x) >> 5;
    int lane = threadIdx.x & 31;
    if (warp >= NPTS) return;
    const float2* src = (const float2*)(X + (size_t)warp * DIMX);
    __half2* dst = (__half2*)(g_xh + (size_t)warp * DIMX);
    float s = 0.f;
#pragma unroll
    for (int t = 0; t < 4; ++t) {
        float2 v = src[lane + 32 * t];
        s = fmaf(v.x, v.x, fmaf(v.y, v.y, s));
        dst[lane + 32 * t] = __floats2half2_rn(v.x, v.y);
    }
#pragma unroll
    for (int o = 16; o > 0; o >>= 1) s += __shfl_xor_sync(0xffffffffu, s, o);
    if (lane == 0) g_sq[warp] = s;
}

// ====== symmetric 64x64 tile-pair screen: f16 MMA, per-chunk f32 promotion ======
__global__ __launch_bounds__(256) void screen_pair_kernel() {
    __shared__ __align__(16) uint8_t smA[64 * 128];   // 64 rows x 64 f16 k-chunk
    __shared__ __align__(16) uint8_t smB[64 * 128];
    __shared__ float smC[64 * 65];
    __shared__ float sqI[64], sqJ[64];
    __shared__ uint4 smH[64];                         // row-side half-1 lists

    const int tid = threadIdx.x;
    const int wid = tid >> 5;
    const int lane = tid & 31;

    // ---- linear pair index -> (ti, tj), ti <= tj ----
    const int k = blockIdx.x;
    int i = (int)(128.5f - sqrtf(128.5f * 128.5f - 2.0f * (float)k));
    if (i < 0) i = 0; if (i > NTILE - 1) i = NTILE - 1;
    while (i > 0 && (i * NTILE - i * (i - 1) / 2) > k) --i;
    while (((i + 1) * NTILE - (i + 1) * i / 2) <= k) ++i;
    const int ti = i;
    const int tj = i + (k - (i * NTILE - i * (i - 1) / 2));
    const int rbI = ti * 64, rbJ = tj * 64;

    if (tid < 64) { sqI[tid] = g_sq[rbI + tid]; sqJ[tid] = g_sq[rbJ + tid]; }

    // staging map: 512 16B-chunks per tile-chunk; thread handles chunk tid and tid+256
    const int rr = tid >> 3, cc = tid & 7;   // r in 0..31, +32 for second

    uint4 pa[2], pb[2];
#pragma unroll
    for (int it = 0; it < 2; ++it) {
        pa[it] = *(const uint4*)(g_xh + (size_t)(rbI + rr + it * 32) * DIMX + cc * 8);
        pb[it] = *(const uint4*)(g_xh + (size_t)(rbJ + rr + it * 32) * DIMX + cc * 8);
    }

    float c[4][4];
#pragma unroll
    for (int j = 0; j < 4; ++j)
#pragma unroll
        for (int q = 0; q < 4; ++q) c[j][q] = 0.f;

    // fragment addressing: warp (wid&3) -> row group, (wid>>2) -> col half
    const int rA = (wid & 3) * 16 + (lane & 15);
    const uint32_t aRowB = smem_u32(smA) + (uint32_t)rA * 128;
    const uint32_t aSw = (uint32_t)(rA & 7);
    const uint32_t aHi = (uint32_t)(lane >> 4);
    const int bLane = (lane & 7) + ((lane >> 4) << 3);
    const uint32_t bRowB = smem_u32(smB) + (uint32_t)bLane * 128;
    const uint32_t bSw = (uint32_t)(lane & 7);
    const uint32_t bHi = (uint32_t)((lane >> 3) & 1);
    const uint32_t bBlk = (uint32_t)(wid >> 2) * 2;   // 16-col block base

    for (int kc = 0; kc < 4; ++kc) {
        __syncthreads();
#pragma unroll
        for (int it = 0; it < 2; ++it) {
            int r = rr + it * 32;
            *(uint4*)(smA + r * 128 + (((uint32_t)cc ^ (r & 7)) << 4)) = pa[it];
            *(uint4*)(smB + r * 128 + (((uint32_t)cc ^ (r & 7)) << 4)) = pb[it];
        }
        __syncthreads();
        if (kc < 3) {
#pragma unroll
            for (int it = 0; it < 2; ++it) {
                pa[it] = *(const uint4*)(g_xh + (size_t)(rbI + rr + it * 32) * DIMX + (kc + 1) * 64 + cc * 8);
                pb[it] = *(const uint4*)(g_xh + (size_t)(rbJ + rr + it * 32) * DIMX + (kc + 1) * 64 + cc * 8);
            }
        }

        // f16 accumulators for this K=64 chunk
        uint32_t d16[4][2];
#pragma unroll
        for (int j = 0; j < 4; ++j) { d16[j][0] = 0u; d16[j][1] = 0u; }

#pragma unroll
        for (int ks = 0; ks < 4; ++ks) {
            uint32_t a0, a1, a2, a3;
            LDSM_X4(a0, a1, a2, a3, aRowB + ((((uint32_t)ks * 2 + aHi) ^ aSw) << 4));
            uint32_t ccB = (((uint32_t)ks * 2 + bHi) ^ bSw) << 4;
#pragma unroll
            for (int p = 0; p < 2; ++p) {
                uint32_t b0, b1, b2, b3;
                LDSM_X4(b0, b1, b2, b3, bRowB + (bBlk + p) * 2048 + ccB);
                MMA16816H(d16[2 * p],     a0, a1, a2, a3, b0, b1);
                MMA16816H(d16[2 * p + 1], a0, a1, a2, a3, b2, b3);
            }
        }

        // promote chunk sums to f32
#pragma unroll
        for (int j = 0; j < 4; ++j) {
            float2 f01 = __half22float2(*reinterpret_cast<__half2*>(&d16[j][0]));
            float2 f23 = __half22float2(*reinterpret_cast<__half2*>(&d16[j][1]));
            c[j][0] += f01.x; c[j][1] += f01.y;
            c[j][2] += f23.x; c[j][3] += f23.y;
        }
    }
    __syncthreads();   // LDSM reads done; safe to write smC/smH below

    // ---- stage C to smem (stride 65) for the col-side scan ----
    const int rloc0 = (wid & 3) * 16 + (lane >> 2), rloc1 = rloc0 + 8;
    const int cq = (wid >> 2) * 32 + 2 * (lane & 3);
#pragma unroll
    for (int j = 0; j < 4; ++j) {
        int col = cq + j * 8;
        smC[rloc0 * 65 + col]     = c[j][0];
        smC[rloc0 * 65 + col + 1] = c[j][1];
        smC[rloc1 * 65 + col]     = c[j][2];
        smC[rloc1 * 65 + col + 1] = c[j][3];
    }

    // ---- row side DIRECT FROM REGISTERS: top-4 over this thread's 8 cols ----
    const int grow0 = rbI + rloc0, grow1 = rbI + rloc1;
    uint32_t l0[PTOP], l1[PTOP];
#pragma unroll
    for (int s = 0; s < PTOP; ++s) { l0[s] = U32MAX; l1[s] = U32MAX; }
#pragma unroll
    for (int j = 0; j < 4; ++j) {
        int c0 = cq + j * 8, c1 = c0 + 1;
        int i0 = rbJ + c0, i1 = rbJ + c1;
        float sq0 = sqJ[c0], sq1 = sqJ[c1];
        if (i0 != grow0) insertK<PTOP>(l0, packkey32(fmaf(-2.f, c[j][0], sq0), i0));
        if (i1 != grow0) insertK<PTOP>(l0, packkey32(fmaf(-2.f, c[j][1], sq1), i1));
        if (i0 != grow1) insertK<PTOP>(l1, packkey32(fmaf(-2.f, c[j][2], sq0), i0));
        if (i1 != grow1) insertK<PTOP>(l1, packkey32(fmaf(-2.f, c[j][3], sq1), i1));
    }
    // quad merge across lane&3 (covers the 32 cols of this warp's half)
#pragma unroll
    for (int d = 1; d < 4; d <<= 1) {
        uint32_t rv0[PTOP], rv1[PTOP];
#pragma unroll
        for (int s = 0; s < PTOP; ++s) {
            rv0[s] = __shfl_xor_sync(0xffffffffu, l0[s], d);
            rv1[s] = __shfl_xor_sync(0xffffffffu, l1[s], d);
        }
        for (int s = 0; s < PTOP; ++s) {
            if (rv0[s] >= l0[PTOP - 1]) break;
            insertK<PTOP>(l0, rv0[s]);
        }
        for (int s = 0; s < PTOP; ++s) {
            if (rv1[s] >= l1[PTOP - 1]) break;
            insertK<PTOP>(l1, rv1[s]);
        }
    }
    // half-1 warps publish their per-row lists
    if ((wid >> 2) == 1 && (lane & 3) == 0) {
        smH[rloc0] = make_uint4(l0[0], l0[1], l0[2], l0[3]);
        smH[rloc1] = make_uint4(l1[0], l1[1], l1[2], l1[3]);
    }
    __syncthreads();   // smH + smC visible

    // half-0 warps fold partner half and store row-side partials
    if ((wid >> 2) == 0 && (lane & 3) == 0) {
        uint4 h0 = smH[rloc0];
        {
            if (h0.x < l0[PTOP - 1]) { insertK<PTOP>(l0, h0.x);
            if (h0.y < l0[PTOP - 1]) { insertK<PTOP>(l0, h0.y);
            if (h0.z < l0[PTOP - 1]) { insertK<PTOP>(l0, h0.z);
            if (h0.w < l0[PTOP - 1]) { insertK<PTOP>(l0, h0.w); } } } }
        }
        uint4 h1 = smH[rloc1];
        {
            if (h1.x < l1[PTOP - 1]) { insertK<PTOP>(l1, h1.x);
            if (h1.y < l1[PTOP - 1]) { insertK<PTOP>(l1, h1.y);
            if (h1.z < l1[PTOP - 1]) { insertK<PTOP>(l1, h1.z);
            if (h1.w < l1[PTOP - 1]) { insertK<PTOP>(l1, h1.w); } } } }
        }
        g_p[(size_t)grow0 * NTILE + tj] = make_uint4(l0[0], l0[1], l0[2], l0[3]);
        g_p[(size_t)grow1 * NTILE + tj] = make_uint4(l1[0], l1[1], l1[2], l1[3]);
    }

    // ---- col side (skip diagonal pair) ----
    if (ti != tj) {
        const int c2 = tid >> 2, h = tid & 3;
        const int grow = rbJ + c2;
        uint32_t l[PTOP];
#pragma unroll
        for (int s = 0; s < PTOP; ++s) l[s] = U32MAX;
#pragma unroll
        for (int s = 0; s < 16; ++s) {
            int rl = h * 16 + s;
            insertK<PTOP>(l, packkey32(fmaf(-2.f, smC[rl * 65 + c2], sqI[rl]), rbI + rl));
        }
#pragma unroll
        for (int d = 1; d < 4; d <<= 1) {
            uint32_t rv[PTOP];
#pragma unroll
            for (int s = 0; s < PTOP; ++s) rv[s] = __shfl_xor_sync(0xffffffffu, l[s], d);
            for (int s = 0; s < PTOP; ++s) {
                if (rv[s] >= l[PTOP - 1]) break;
                insertK<PTOP>(l, rv[s]);
            }
        }
        if (h == 0)
            g_p[(size_t)grow * NTILE + ti] = make_uint4(l[0], l[1], l[2], l[3]);
    }
}

// ===== fused: merge 128 partial lists -> exact fp32 re-rank -> lid_X ->
//        z-distances -> lid_Z -> block sum =====
__global__ __launch_bounds__(256) void merge_rerank_z_kernel(const float* __restrict__ X,
                                                             const float* __restrict__ Z) {
    __shared__ float bsum[8];
    const int warp = (blockIdx.x * blockDim.x + threadIdx.x) >> 5;
    const int lane = threadIdx.x & 31;
    const int wid = threadIdx.x >> 5;
    const int row = warp;

    uint32_t l[GTOP];
#pragma unroll
    for (int s = 0; s < GTOP; ++s) l[s] = U32MAX;
#pragma unroll
    for (int q = 0; q < 4; ++q) {
        uint4 v = g_p[(size_t)row * NTILE + lane + q * 32];
        if (v.x >= l[GTOP - 1]) continue;
        insertK<GTOP>(l, v.x);
        if (v.y >= l[GTOP - 1]) continue;
        insertK<GTOP>(l, v.y);
        if (v.z >= l[GTOP - 1]) continue;
        insertK<GTOP>(l, v.z);
        if (v.w < l[GTOP - 1]) insertK<GTOP>(l, v.w);
    }
#pragma unroll
    for (int d = 1; d < 32; d <<= 1) {
        uint32_t rv[GTOP];
#pragma unroll
        for (int s = 0; s < GTOP; ++s) rv[s] = __shfl_xor_sync(0xffffffffu, l[s], d);
        for (int s = 0; s < GTOP; ++s) {
            if (rv[s] >= l[GTOP - 1]) break;
            insertK<GTOP>(l, rv[s]);
        }
    }

    float xi[8];
#pragma unroll
    for (int t = 0; t < 8; ++t) xi[t] = X[(size_t)row * DIMX + lane + 32 * t];
    const float sqr = g_sq[row];

    float lv[KNN]; int li[KNN];
#pragma unroll
    for (int s = 0; s < KNN; ++s) { lv[s] = 3.4e38f; li[s] = 0x7fffffff; }

#pragma unroll
    for (int s = 0; s < GTOP; ++s) {
        int j = (int)(l[s] & IDXMASK);
        const float* xr = X + (size_t)j * DIMX;
        float d = 0.f;
#pragma unroll
        for (int t = 0; t < 8; ++t) d = fmaf(xi[t], xr[lane + 32 * t], d);
#pragma unroll
        for (int o = 16; o > 0; o >>= 1) d += __shfl_xor_sync(0xffffffffu, d, o);
        insert5(lv, li, sqr + g_sq[j] - 2.f * d, j);
    }

    float lidX;
    {
        float vK = sqrtf(fmaxf(lv[KNN - 1], 0.f)) + EPSF;
        float lgK = log10f(vK);
        lidX = 0.f;
#pragma unroll
        for (int s = 0; s < KNN; ++s)
            lidX += lgK - log10f(sqrtf(fmaxf(lv[s], 0.f)) + EPSF);
    }

    float z0 = Z[(size_t)row * DIMZ + lane];
    float z1 = Z[(size_t)row * DIMZ + 32 + lane];
    float e[KNN];
#pragma unroll
    for (int s = 0; s < KNN; ++s) {
        int m = li[s];
        float d0 = z0 - Z[(size_t)m * DIMZ + lane];
        float d1 = z1 - Z[(size_t)m * DIMZ + 32 + lane];
        float ss = fmaf(d0, d0, d1 * d1);
#pragma unroll
        for (int o = 16; o > 0; o >>= 1) ss += __shfl_xor_sync(0xffffffffu, ss, o);
        e[s] = sqrtf(ss) + EPSF;
    }
    float lgK = log10f(e[KNN - 1]);
    float lidZ = 0.f;
#pragma unroll
    for (int s = 0; s < KNN; ++s) lidZ += lgK - log10f(e[s]);
    float d = lidX - lidZ;

    if (lane == 0) bsum[wid] = d * d;
    __syncthreads();
    if (threadIdx.x == 0) {
        float s = 0.f;
#pragma unroll
        for (int w = 0; w < 8; ++w) s += bsum[w];
        g_bsum[blockIdx.x] = s;
    }
}

// ================= final deterministic reduction =================
__global__ void final_reduce(float* __restrict__ out) {
    __shared__ float sh[256];
    int t = threadIdx.x;
    float s = g_bsum[t] + g_bsum[t + 256] + g_bsum[t + 512] + g_bsum[t + 768];
    sh[t] = s;
    __syncthreads();
    for (int o = 128; o > 0; o >>= 1) {
        if (t < o) sh[t] += sh[t + o];
        __syncthreads();
    }
    if (t == 0) out[0] = sh[0] * (1.f / ((float)NPTS * KNN * 10.f));
}

extern "C" void kernel_launch(void* const* d_in, const int* in_sizes, int n_in,
                              void* d_out, int out_size) {
    const float* X = (const float*)d_in[0];   // (8192, 256)
    const float* Z = (const float*)d_in[1];   // (8192, 64)
    float* out = (float*)d_out;

    cvtsq_kernel<<<NPTS / 8, 256>>>(X);
    screen_pair_kernel<<<NPAIRS, 256>>>();
    merge_rerank_z_kernel<<<NPTS / 8, 256>>>(X, Z);
    final_reduce<<<1, 256>>>(out);
}

// round 17
// speedup vs baseline: 1.0668x; 1.0668x over previous
#include <cuda_runtime.h>
#include <cuda_bf16.h>
#include <cstdint>

#define NPTS 8192
#define DIMX 256
#define DIMZ 64
#define KNN  5
#define EPSF 1e-7f

#define NTILE 128                          // 8192 / 64 row-tiles
#define NPAIRS (NTILE * (NTILE + 1) / 2)   // 8256
#define PTOP 4
#define GTOP 8
#define U32MAX 0xFFFFFFFFu
#define IDXMASK 0x1FFFu                    // 13 bits: idx < 8192

// ---- scratch ----
__device__ float g_sq[NPTS];
__device__ __nv_bfloat16 g_xbf[NPTS * DIMX];
__device__ uint4 g_p[(size_t)NPTS * NTILE];   // 16.8 MB: 4 packed u32 keys per (row,tile)
__device__ float g_bsum[1024];

__device__ __forceinline__ uint32_t smem_u32(const void* p) {
    uint32_t a;
    asm("{ .reg .u64 t; cvta.to.shared.u64 t, %1; cvt.u32.u64 %0, t; }" : "=r"(a) : "l"(p));
    return a;
}

#define LDSM_X4(r0, r1, r2, r3, addr) \
    asm volatile("ldmatrix.sync.aligned.m8n8.x4.shared.b16 {%0,%1,%2,%3}, [%4];" \
                 : "=r"(r0), "=r"(r1), "=r"(r2), "=r"(r3) : "r"(addr))

#define MMA16816(c, a0, a1, a2, a3, b0, b1) \
    asm volatile("mma.sync.aligned.m16n8k16.row.col.f32.bf16.bf16.f32 " \
                 "{%0,%1,%2,%3}, {%4,%5,%6,%7}, {%8,%9}, {%0,%1,%2,%3};" \
                 : "+f"((c)[0]), "+f"((c)[1]), "+f"((c)[2]), "+f"((c)[3]) \
                 : "r"(a0), "r"(a1), "r"(a2), "r"(a3), "r"(b0), "r"(b1))

// monotone float->u32, top 19 bits kept; low 13 bits = idx.
// u32 '<' == (quantized value, idx) lexicographic.
__device__ __forceinline__ uint32_t packkey32(float v, int idx) {
    uint32_t u = __float_as_uint(v);
    u = (u >> 31) ? ~u : (u | 0x80000000u);
    return (u & ~IDXMASK) | (uint32_t)idx;
}
template<int NL>
__device__ __forceinline__ void insertK(uint32_t l[NL], uint32_t v) {
    if (v < l[NL - 1]) {
        l[NL - 1] = v;
#pragma unroll
        for (int s = NL - 1; s > 0; --s)
            if (l[s] < l[s - 1]) { uint32_t t = l[s]; l[s] = l[s - 1]; l[s - 1] = t; }
    }
}
__device__ __forceinline__ bool lessp(float v, int i, float v2, int i2) {
    return (v < v2) || (v == v2 && i < i2);
}
__device__ __forceinline__ void insert5(float lv[KNN], int li[KNN], float v, int idx) {
    if (lessp(v, idx, lv[KNN - 1], li[KNN - 1])) {
        lv[KNN - 1] = v; li[KNN - 1] = idx;
#pragma unroll
        for (int s = KNN - 1; s > 0; --s) {
            if (lessp(lv[s], li[s], lv[s - 1], li[s - 1])) {
                float tv = lv[s]; lv[s] = lv[s - 1]; lv[s - 1] = tv;
                int   ti = li[s]; li[s] = li[s - 1]; li[s - 1] = ti;
            }
        }
    }
}

// ================= fused fp32->bf16 + squared row norms =================
__global__ void cvtsq_kernel(const float* __restrict__ X) {
    int warp = (blockIdx.x * blockDim.x + threadIdx.x) >> 5;
    int lane = threadIdx.x & 31;
    if (warp >= NPTS) return;
    const float2* src = (const float2*)(X + (size_t)warp * DIMX);
    __nv_bfloat162* dst = (__nv_bfloat162*)(g_xbf + (size_t)warp * DIMX);
    float s = 0.f;
#pragma unroll
    for (int t = 0; t < 4; ++t) {
        float2 v = src[lane + 32 * t];
        s = fmaf(v.x, v.x, fmaf(v.y, v.y, s));
        dst[lane + 32 * t] = __floats2bfloat162_rn(v.x, v.y);
    }
#pragma unroll
    for (int o = 16; o > 0; o >>= 1) s += __shfl_xor_sync(0xffffffffu, s, o);
    if (lane == 0) g_sq[warp] = s;
}

// ====== symmetric 64x64 tile-pair screen: register-direct row side ======
__global__ __launch_bounds__(256) void screen_pair_kernel() {
    __shared__ __align__(16) uint8_t smA[64 * 128];   // 64 rows x 64 bf16 k-chunk
    __shared__ __align__(16) uint8_t smB[64 * 128];
    __shared__ float smC[64 * 65];
    __shared__ float sqI[64], sqJ[64];
    __shared__ uint4 smH[64];                         // row-side half-1 lists

    const int tid = threadIdx.x;
    const int wid = tid >> 5;
    const int lane = tid & 31;

    // ---- linear pair index -> (ti, tj), ti <= tj ----
    const int k = blockIdx.x;
    int i = (int)(128.5f - sqrtf(128.5f * 128.5f - 2.0f * (float)k));
    if (i < 0) i = 0; if (i > NTILE - 1) i = NTILE - 1;
    while (i > 0 && (i * NTILE - i * (i - 1) / 2) > k) --i;
    while (((i + 1) * NTILE - (i + 1) * i / 2) <= k) ++i;
    const int ti = i;
    const int tj = i + (k - (i * NTILE - i * (i - 1) / 2));
    const int rbI = ti * 64, rbJ = tj * 64;

    if (tid < 64) { sqI[tid] = g_sq[rbI + tid]; sqJ[tid] = g_sq[rbJ + tid]; }

    // staging map: 512 16B-chunks per tile-chunk; thread handles chunk tid and tid+256
    const int rr = tid >> 3, cc = tid & 7;   // r in 0..31, +32 for second

    uint4 pa[2], pb[2];
#pragma unroll
    for (int it = 0; it < 2; ++it) {
        pa[it] = *(const uint4*)(g_xbf + (size_t)(rbI + rr + it * 32) * DIMX + cc * 8);
        pb[it] = *(const uint4*)(g_xbf + (size_t)(rbJ + rr + it * 32) * DIMX + cc * 8);
    }

    float c[4][4];
#pragma unroll
    for (int j = 0; j < 4; ++j)
#pragma unroll
        for (int q = 0; q < 4; ++q) c[j][q] = 0.f;

    // fragment addressing: warp (wid&3) -> row group, (wid>>2) -> col half
    const int rA = (wid & 3) * 16 + (lane & 15);
    const uint32_t aRowB = smem_u32(smA) + (uint32_t)rA * 128;
    const uint32_t aSw = (uint32_t)(rA & 7);
    const uint32_t aHi = (uint32_t)(lane >> 4);
    const int bLane = (lane & 7) + ((lane >> 4) << 3);
    const uint32_t bRowB = smem_u32(smB) + (uint32_t)bLane * 128;
    const uint32_t bSw = (uint32_t)(lane & 7);
    const uint32_t bHi = (uint32_t)((lane >> 3) & 1);
    const uint32_t bBlk = (uint32_t)(wid >> 2) * 2;   // 16-col block base

    for (int kc = 0; kc < 4; ++kc) {
        __syncthreads();
#pragma unroll
        for (int it = 0; it < 2; ++it) {
            int r = rr + it * 32;
            *(uint4*)(smA + r * 128 + (((uint32_t)cc ^ (r & 7)) << 4)) = pa[it];
            *(uint4*)(smB + r * 128 + (((uint32_t)cc ^ (r & 7)) << 4)) = pb[it];
        }
        __syncthreads();
        if (kc < 3) {
#pragma unroll
            for (int it = 0; it < 2; ++it) {
                pa[it] = *(const uint4*)(g_xbf + (size_t)(rbI + rr + it * 32) * DIMX + (kc + 1) * 64 + cc * 8);
                pb[it] = *(const uint4*)(g_xbf + (size_t)(rbJ + rr + it * 32) * DIMX + (kc + 1) * 64 + cc * 8);
            }
        }
#pragma unroll
        for (int ks = 0; ks < 4; ++ks) {
            uint32_t a0, a1, a2, a3;
            LDSM_X4(a0, a1, a2, a3, aRowB + ((((uint32_t)ks * 2 + aHi) ^ aSw) << 4));
            uint32_t ccB = (((uint32_t)ks * 2 + bHi) ^ bSw) << 4;
#pragma unroll
            for (int p = 0; p < 2; ++p) {
                uint32_t b0, b1, b2, b3;
                LDSM_X4(b0, b1, b2, b3, bRowB + (bBlk + p) * 2048 + ccB);
                MMA16816(c[2 * p],     a0, a1, a2, a3, b0, b1);
                MMA16816(c[2 * p + 1], a0, a1, a2, a3, b2, b3);
            }
        }
    }
    __syncthreads();   // LDSM reads done; safe to write smC/smH below

    // ---- stage C to smem (stride 65) for the col-side scan ----
    const int rloc0 = (wid & 3) * 16 + (lane >> 2), rloc1 = rloc0 + 8;
    const int cq = (wid >> 2) * 32 + 2 * (lane & 3);
#pragma unroll
    for (int j = 0; j < 4; ++j) {
        int col = cq + j * 8;
        smC[rloc0 * 65 + col]     = c[j][0];
        smC[rloc0 * 65 + col + 1] = c[j][1];
        smC[rloc1 * 65 + col]     = c[j][2];
        smC[rloc1 * 65 + col + 1] = c[j][3];
    }

    // ---- row side DIRECT FROM REGISTERS: top-4 over this thread's 8 cols ----
    const int grow0 = rbI + rloc0, grow1 = rbI + rloc1;
    uint32_t l0[PTOP], l1[PTOP];
#pragma unroll
    for (int s = 0; s < PTOP; ++s) { l0[s] = U32MAX; l1[s] = U32MAX; }
#pragma unroll
    for (int j = 0; j < 4; ++j) {
        int c0 = cq + j * 8, c1 = c0 + 1;
        int i0 = rbJ + c0, i1 = rbJ + c1;
        float sq0 = sqJ[c0], sq1 = sqJ[c1];
        if (i0 != grow0) insertK<PTOP>(l0, packkey32(fmaf(-2.f, c[j][0], sq0), i0));
        if (i1 != grow0) insertK<PTOP>(l0, packkey32(fmaf(-2.f, c[j][1], sq1), i1));
        if (i0 != grow1) insertK<PTOP>(l1, packkey32(fmaf(-2.f, c[j][2], sq0), i0));
        if (i1 != grow1) insertK<PTOP>(l1, packkey32(fmaf(-2.f, c[j][3], sq1), i1));
    }
    // quad merge across lane&3 (covers the 32 cols of this warp's half)
#pragma unroll
    for (int d = 1; d < 4; d <<= 1) {
        uint32_t rv0[PTOP], rv1[PTOP];
#pragma unroll
        for (int s = 0; s < PTOP; ++s) {
            rv0[s] = __shfl_xor_sync(0xffffffffu, l0[s], d);
            rv1[s] = __shfl_xor_sync(0xffffffffu, l1[s], d);
        }
        for (int s = 0; s < PTOP; ++s) {
            if (rv0[s] >= l0[PTOP - 1]) break;
            insertK<PTOP>(l0, rv0[s]);
        }
        for (int s = 0; s < PTOP; ++s) {
            if (rv1[s] >= l1[PTOP - 1]) break;
            insertK<PTOP>(l1, rv1[s]);
        }
    }
    // half-1 warps publish their per-row lists
    if ((wid >> 2) == 1 && (lane & 3) == 0) {
        smH[rloc0] = make_uint4(l0[0], l0[1], l0[2], l0[3]);
        smH[rloc1] = make_uint4(l1[0], l1[1], l1[2], l1[3]);
    }
    __syncthreads();   // smH + smC visible

    // half-0 warps fold partner half and store row-side partials
    if ((wid >> 2) == 0 && (lane & 3) == 0) {
        uint4 h0 = smH[rloc0];
        {
            if (h0.x < l0[PTOP - 1]) { insertK<PTOP>(l0, h0.x);
            if (h0.y < l0[PTOP - 1]) { insertK<PTOP>(l0, h0.y);
            if (h0.z < l0[PTOP - 1]) { insertK<PTOP>(l0, h0.z);
            if (h0.w < l0[PTOP - 1]) { insertK<PTOP>(l0, h0.w); } } } }
        }
        uint4 h1 = smH[rloc1];
        {
            if (h1.x < l1[PTOP - 1]) { insertK<PTOP>(l1, h1.x);
            if (h1.y < l1[PTOP - 1]) { insertK<PTOP>(l1, h1.y);
            if (h1.z < l1[PTOP - 1]) { insertK<PTOP>(l1, h1.z);
            if (h1.w < l1[PTOP - 1]) { insertK<PTOP>(l1, h1.w); } } } }
        }
        g_p[(size_t)grow0 * NTILE + tj] = make_uint4(l0[0], l0[1], l0[2], l0[3]);
        g_p[(size_t)grow1 * NTILE + tj] = make_uint4(l1[0], l1[1], l1[2], l1[3]);
    }

    // ---- col side (unchanged; skip diagonal pair) ----
    if (ti != tj) {
        const int c2 = tid >> 2, h = tid & 3;
        const int grow = rbJ + c2;
        uint32_t l[PTOP];
#pragma unroll
        for (int s = 0; s < PTOP; ++s) l[s] = U32MAX;
#pragma unroll
        for (int s = 0; s < 16; ++s) {
            int rl = h * 16 + s;
            insertK<PTOP>(l, packkey32(fmaf(-2.f, smC[rl * 65 + c2], sqI[rl]), rbI + rl));
        }
#pragma unroll
        for (int d = 1; d < 4; d <<= 1) {
            uint32_t rv[PTOP];
#pragma unroll
            for (int s = 0; s < PTOP; ++s) rv[s] = __shfl_xor_sync(0xffffffffu, l[s], d);
            for (int s = 0; s < PTOP; ++s) {
                if (rv[s] >= l[PTOP - 1]) break;
                insertK<PTOP>(l, rv[s]);
            }
        }
        if (h == 0)
            g_p[(size_t)grow * NTILE + ti] = make_uint4(l[0], l[1], l[2], l[3]);
    }
}

// ===== fused: merge 128 partial lists -> exact fp32 re-rank -> lid_X ->
//        z-distances -> lid_Z -> block sum =====
__global__ __launch_bounds__(256) void merge_rerank_z_kernel(const float* __restrict__ X,
                                                             const float* __restrict__ Z) {
    __shared__ float bsum[8];
    const int warp = (blockIdx.x * blockDim.x + threadIdx.x) >> 5;
    const int lane = threadIdx.x & 31;
    const int wid = threadIdx.x >> 5;
    const int row = warp;

    uint32_t l[GTOP];
#pragma unroll
    for (int s = 0; s < GTOP; ++s) l[s] = U32MAX;
#pragma unroll
    for (int q = 0; q < 4; ++q) {
        uint4 v = g_p[(size_t)row * NTILE + lane + q * 32];
        if (v.x >= l[GTOP - 1]) continue;
        insertK<GTOP>(l, v.x);
        if (v.y >= l[GTOP - 1]) continue;
        insertK<GTOP>(l, v.y);
        if (v.z >= l[GTOP - 1]) continue;
        insertK<GTOP>(l, v.z);
        if (v.w < l[GTOP - 1]) insertK<GTOP>(l, v.w);
    }
#pragma unroll
    for (int d = 1; d < 32; d <<= 1) {
        uint32_t rv[GTOP];
#pragma unroll
        for (int s = 0; s < GTOP; ++s) rv[s] = __shfl_xor_sync(0xffffffffu, l[s], d);
        for (int s = 0; s < GTOP; ++s) {
            if (rv[s] >= l[GTOP - 1]) break;
            insertK<GTOP>(l, rv[s]);
        }
    }

    float xi[8];
#pragma unroll
    for (int t = 0; t < 8; ++t) xi[t] = X[(size_t)row * DIMX + lane + 32 * t];
    const float sqr = g_sq[row];

    float lv[KNN]; int li[KNN];
#pragma unroll
    for (int s = 0; s < KNN; ++s) { lv[s] = 3.4e38f; li[s] = 0x7fffffff; }

#pragma unroll
    for (int s = 0; s < GTOP; ++s) {
        int j = (int)(l[s] & IDXMASK);
        const float* xr = X + (size_t)j * DIMX;
        float d = 0.f;
#pragma unroll
        for (int t = 0; t < 8; ++t) d = fmaf(xi[t], xr[lane + 32 * t], d);
#pragma unroll
        for (int o = 16; o > 0; o >>= 1) d += __shfl_xor_sync(0xffffffffu, d, o);
        insert5(lv, li, sqr + g_sq[j] - 2.f * d, j);
    }

    float lidX;
    {
        float vK = sqrtf(fmaxf(lv[KNN - 1], 0.f)) + EPSF;
        float lgK = log10f(vK);
        lidX = 0.f;
#pragma unroll
        for (int s = 0; s < KNN; ++s)
            lidX += lgK - log10f(sqrtf(fmaxf(lv[s], 0.f)) + EPSF);
    }

    float z0 = Z[(size_t)row * DIMZ + lane];
    float z1 = Z[(size_t)row * DIMZ + 32 + lane];
    float e[KNN];
#pragma unroll
    for (int s = 0; s < KNN; ++s) {
        int m = li[s];
        float d0 = z0 - Z[(size_t)m * DIMZ + lane];
        float d1 = z1 - Z[(size_t)m * DIMZ + 32 + lane];
        float ss = fmaf(d0, d0, d1 * d1);
#pragma unroll
        for (int o = 16; o > 0; o >>= 1) ss += __shfl_xor_sync(0xffffffffu, ss, o);
        e[s] = sqrtf(ss) + EPSF;
    }
    float lgK = log10f(e[KNN - 1]);
    float lidZ = 0.f;
#pragma unroll
    for (int s = 0; s < KNN; ++s) lidZ += lgK - log10f(e[s]);
    float d = lidX - lidZ;

    if (lane == 0) bsum[wid] = d * d;
    __syncthreads();
    if (threadIdx.x == 0) {
        float s = 0.f;
#pragma unroll
        for (int w = 0; w < 8; ++w) s += bsum[w];
        g_bsum[blockIdx.x] = s;
    }
}

// ================= final deterministic reduction =================
__global__ void final_reduce(float* __restrict__ out) {
    __shared__ float sh[256];
    int t = threadIdx.x;
    float s = g_bsum[t] + g_bsum[t + 256] + g_bsum[t + 512] + g_bsum[t + 768];
    sh[t] = s;
    __syncthreads();
    for (int o = 128; o > 0; o >>= 1) {
        if (t < o) sh[t] += sh[t + o];
        __syncthreads();
    }
    if (t == 0) out[0] = sh[0] * (1.f / ((float)NPTS * KNN * 10.f));
}

extern "C" void kernel_launch(void* const* d_in, const int* in_sizes, int n_in,
                              void* d_out, int out_size) {
    const float* X = (const float*)d_in[0];   // (8192, 256)
    const float* Z = (const float*)d_in[1];   // (8192, 64)
    float* out = (float*)d_out;

    cvtsq_kernel<<<NPTS / 8, 256>>>(X);
    screen_pair_kernel<<<NPAIRS, 256>>>();
    merge_rerank_z_kernel<<<NPTS / 8, 256>>>(X, Z);
    final_reduce<<<1, 256>>>(out);
}